// round 13
// baseline (speedup 1.0000x reference)
#include <cuda_runtime.h>
#include <cuda_fp16.h>
#include <cstdint>

#define Bn 8
#define Ln 2500
#define Dn 512
#define Yn 8921
#define YT 64           // y per CTA
#define LT 192          // l per CTA tile (4 warps x 48)
#define KC 64           // k per chunk (fp16 elems)
#define NCH (Dn / KC)   // 8 chunks
#define NTILES 14       // ceil(2500/192)
#define NT 256
#define ROWB 144                    // smem row stride bytes (128 data + 16 pad)
#define TW (64 * ROWB)              // 9216  (U/F tiles: 64 rows)
#define TX (192 * ROWB)             // 27648 (X tile: 192 rows)
#define OFF_U 0
#define OFF_F TW
#define OFF_X (2 * TW)
#define BUF_BYTES (2 * TW + TX)     // 46080
#define SMEM_BYTES (2 * BUF_BYTES)  // 92160 -> 2 CTAs/SM

// fp16 scratch (device globals; no runtime alloc)
__device__ __half g_u16[(size_t)Yn * Dn];
__device__ __half g_f16[(size_t)Yn * Dn];
__device__ __half g_x16[(size_t)Bn * Ln * Dn];

// mma.sync m16n8k16 fp16 inputs, fp32 accumulate (plain sm_80+ instruction)
#define MMA(D, A, B0, B1)                                                   \
    asm volatile(                                                           \
        "mma.sync.aligned.m16n8k16.row.col.f32.f16.f16.f32 "                \
        "{%0,%1,%2,%3}, {%4,%5,%6,%7}, {%8,%9}, {%0,%1,%2,%3};"             \
        : "+f"((D)[0]), "+f"((D)[1]), "+f"((D)[2]), "+f"((D)[3])            \
        : "r"((A)[0]), "r"((A)[1]), "r"((A)[2]), "r"((A)[3]),               \
          "r"(B0), "r"(B1))

#define LDSM4(R0, R1, R2, R3, addr)                                         \
    asm volatile(                                                           \
        "ldmatrix.sync.aligned.m8n8.x4.shared.b16 {%0,%1,%2,%3}, [%4];"     \
        : "=r"(R0), "=r"(R1), "=r"(R2), "=r"(R3) : "r"(addr))

static __device__ __forceinline__ void cp16(uint32_t dst, const void* src,
                                            bool v) {
    int sz = v ? 16 : 0;   // sz=0 -> zero-fill 16B, no gmem read
    asm volatile("cp.async.cg.shared.global [%0], [%1], 16, %2;"
                 :: "r"(dst), "l"(src), "r"(sz));
}
template <int N>
static __device__ __forceinline__ void cpwait() {
    asm volatile("cp.async.wait_group %0;" :: "n"(N) : "memory");
}
static __device__ __forceinline__ uint32_t smem_u32(const void* p) {
    uint32_t a;
    asm("{ .reg .u64 t; cvta.to.shared.u64 t, %1; cvt.u32.u64 %0, t; }"
        : "=r"(a) : "l"(p));
    return a;
}

// stage one k-chunk: U,F [64 x 64] + X [192 x 64] fp16 -> padded smem
static __device__ __forceinline__ void stage_chunk(
    uint32_t bufaddr, int tid, int b, int y0, int l0, int k0)
{
    const __half* u = g_u16 + (size_t)y0 * Dn;
    const __half* f = g_f16 + (size_t)y0 * Dn;
    const int limW = Yn - y0;
#pragma unroll
    for (int j = 0; j < 2; j++) {
        int idx = tid + j * NT;              // 0..511 = 64 rows x 8 segs
        int r = idx >> 3, seg = idx & 7;     // seg = 16B (8 fp16)
        uint32_t doff = (uint32_t)(r * ROWB + seg * 16);
        cp16(bufaddr + OFF_U + doff, u + (size_t)r * Dn + k0 + seg * 8, r < limW);
        cp16(bufaddr + OFF_F + doff, f + (size_t)r * Dn + k0 + seg * 8, r < limW);
    }
    const __half* xs = g_x16 + ((size_t)b * Ln + l0) * Dn;
    const int limX = Ln - l0;
#pragma unroll
    for (int j = 0; j < 6; j++) {
        int idx = tid + j * NT;              // 0..1535 = 192 rows x 8 segs
        int r = idx >> 3, seg = idx & 7;
        cp16(bufaddr + OFF_X + (uint32_t)(r * ROWB + seg * 16),
             xs + (size_t)r * Dn + k0 + seg * 8, r < limX);
    }
    asm volatile("cp.async.commit_group;" ::: "memory");
}

__global__ __launch_bounds__(NT, 2)
void attn_mma_kernel(const float* __restrict__ f_b, float* __restrict__ out)
{
    extern __shared__ float smem[];
    const uint32_t sbase = smem_u32(smem);
    const int tid  = threadIdx.x;
    const int lane = tid & 31;
    const int g    = lane >> 2;          // group id 0..7
    const int tg   = lane & 3;           // thread in group 0..3
    const int wid  = tid >> 5;
    const int wy   = wid >> 2;           // warp y index 0..1 (32 y each)
    const int wl   = wid & 3;            // warp l index 0..3 (48 l each)
    const int b    = blockIdx.y;
    const int y0   = blockIdx.x * YT;

    // ldmatrix per-lane address components (bytes)
    const int quad = lane >> 3, r8 = lane & 7;
    const uint32_t laneA = (uint32_t)((r8 + (quad & 1) * 8) * ROWB + (quad >> 1) * 16);
    const uint32_t laneB = (uint32_t)((r8 + (quad >> 1) * 8) * ROWB + (quad & 1) * 16);
    uint32_t aRow[2], bRow[3];
#pragma unroll
    for (int a = 0; a < 2; a++)  aRow[a]  = (uint32_t)((wy * 32 + a * 16) * ROWB) + laneA;
#pragma unroll
    for (int cp = 0; cp < 3; cp++) bRow[cp] = (uint32_t)((wl * 48 + cp * 16) * ROWB) + laneB;

    // running softmax sums for this thread's 4 y rows
    float ss[4] = {0.f, 0.f, 0.f, 0.f};
    float zz[4] = {0.f, 0.f, 0.f, 0.f};

    stage_chunk(sbase, tid, b, y0, 0, 0);   // tile 0, chunk 0 -> buf 0

    for (int t = 0; t < NTILES; t++) {
        const int l0 = t * LT;

        float dS[2][6][4], dT[2][6][4];
#pragma unroll
        for (int a = 0; a < 2; a++)
#pragma unroll
            for (int c = 0; c < 6; c++)
#pragma unroll
                for (int r = 0; r < 4; r++) { dS[a][c][r] = 0.f; dT[a][c][r] = 0.f; }

        for (int ch = 0; ch < NCH; ch++) {
            cpwait<0>();
            __syncthreads();   // all warps done with the other buffer

            const bool last_all = (t == NTILES - 1) && (ch == NCH - 1);
            if (!last_all) {
                // prefetch next chunk (possibly next tile's chunk 0);
                // overlaps with this chunk's mma block
                int nl0 = (ch == NCH - 1) ? l0 + LT : l0;
                int nk0 = (ch == NCH - 1) ? 0 : (ch + 1) * KC;
                stage_chunk(sbase + ((ch + 1) & 1) * BUF_BYTES, tid, b, y0, nl0, nk0);
            }

            const uint32_t bufb = sbase + (ch & 1) * BUF_BYTES;

#pragma unroll
            for (int ka = 0; ka < 4; ka++) {        // four k16 steps
                const uint32_t kao = (uint32_t)(ka * 32);
                uint32_t au[2][4], af[2][4];
#pragma unroll
                for (int a = 0; a < 2; a++) {
                    uint32_t ab = bufb + aRow[a] + kao;
                    LDSM4(au[a][0], au[a][1], au[a][2], au[a][3], ab + OFF_U);
                    LDSM4(af[a][0], af[a][1], af[a][2], af[a][3], ab + OFF_F);
                }
                uint32_t bx[6][2];
#pragma unroll
                for (int cp = 0; cp < 3; cp++) {
                    uint32_t bb = bufb + OFF_X + bRow[cp] + kao;
                    LDSM4(bx[2*cp][0], bx[2*cp][1], bx[2*cp+1][0], bx[2*cp+1][1], bb);
                }
#pragma unroll
                for (int a = 0; a < 2; a++)
#pragma unroll
                    for (int c = 0; c < 6; c++) MMA(dS[a][c], au[a], bx[c][0], bx[c][1]);
#pragma unroll
                for (int a = 0; a < 2; a++)
#pragma unroll
                    for (int c = 0; c < 6; c++) MMA(dT[a][c], af[a], bx[c][0], bx[c][1]);
            }
        }

        // epilogue (regs only) — overlaps the in-flight prefetch of next tile
#pragma unroll
        for (int a = 0; a < 2; a++)
#pragma unroll
            for (int c = 0; c < 6; c++)
#pragma unroll
                for (int r2 = 0; r2 < 2; r2++) {
                    int le = l0 + wl * 48 + c * 8 + 2 * tg;
                    float s0 = dS[a][c][r2 * 2],     t0 = dT[a][c][r2 * 2];
                    float s1 = dS[a][c][r2 * 2 + 1], t1 = dT[a][c][r2 * 2 + 1];
                    if (le < Ln)     { float e = __expf(s0); ss[a*2+r2] += e; zz[a*2+r2] += e * t0; }
                    if (le + 1 < Ln) { float e = __expf(s1); ss[a*2+r2] += e; zz[a*2+r2] += e * t1; }
                }
    }

    // reduce across the 4 lanes sharing each y row (tg dimension)
#pragma unroll
    for (int i = 0; i < 4; i++) {
        ss[i] += __shfl_xor_sync(0xffffffffu, ss[i], 1);
        ss[i] += __shfl_xor_sync(0xffffffffu, ss[i], 2);
        zz[i] += __shfl_xor_sync(0xffffffffu, zz[i], 1);
        zz[i] += __shfl_xor_sync(0xffffffffu, zz[i], 2);
    }

    // cross-warp (wl) reduction via smem (all staging finished by now)
    __syncthreads();
    float* sred = smem;          // [4 wl][64]
    float* zred = smem + 256;    // [4 wl][64]
    if (tg == 0) {
#pragma unroll
        for (int i = 0; i < 4; i++) {
            int yl = wy * 32 + (i >> 1) * 16 + (i & 1) * 8 + g;
            sred[wl * 64 + yl] = ss[i];
            zred[wl * 64 + yl] = zz[i];
        }
    }
    __syncthreads();
    if (tid < YT) {
        int yg = y0 + tid;
        if (yg < Yn) {
            float s = sred[tid] + sred[64 + tid] + sred[128 + tid] + sred[192 + tid];
            float z = zred[tid] + zred[64 + tid] + zred[128 + tid] + zred[192 + tid];
            out[(size_t)b * Yn + yg] = z / s + f_b[yg];
        }
    }
}

// ---------------- prepass: fp32 -> fp16 ----------------
__global__ void prep_w(const float* __restrict__ U, const float* __restrict__ F)
{
    const size_t n = (size_t)Yn * Dn;
    for (size_t i = (size_t)blockIdx.x * blockDim.x + threadIdx.x; i < n;
         i += (size_t)gridDim.x * blockDim.x) {
        g_u16[i] = __float2half_rn(U[i]);
        g_f16[i] = __float2half_rn(F[i]);
    }
}

__global__ void prep_x(const float* __restrict__ x)
{
    const size_t n = (size_t)Bn * Ln * Dn;
    for (size_t i = (size_t)blockIdx.x * blockDim.x + threadIdx.x; i < n;
         i += (size_t)gridDim.x * blockDim.x)
        g_x16[i] = __float2half_rn(x[i]);
}

// mean BCE-with-logits; single block, fixed-order -> deterministic
__global__ void bce_kernel(const float* __restrict__ y,
                           const float* __restrict__ t,
                           float* __restrict__ loss_out, int n)
{
    __shared__ float red[1024];
    float acc = 0.f;
    for (int i = threadIdx.x; i < n; i += 1024) {
        float v  = y[i];
        float tt = t[i];
        acc += fmaxf(v, 0.f) - v * tt + log1pf(__expf(-fabsf(v)));
    }
    red[threadIdx.x] = acc;
    __syncthreads();
    for (int s = 512; s > 0; s >>= 1) {
        if (threadIdx.x < s) red[threadIdx.x] += red[threadIdx.x + s];
        __syncthreads();
    }
    if (threadIdx.x == 0) loss_out[0] = red[0] / (float)n;
}

extern "C" void kernel_launch(void* const* d_in, const int* in_sizes, int n_in,
                              void* d_out, int out_size)
{
    const float* x      = (const float*)d_in[0];
    const float* target = (const float*)d_in[1];
    // d_in[2] = text_inputs (unused)
    const float* U_w    = (const float*)d_in[3];
    const float* F_w    = (const float*)d_in[4];
    const float* f_b    = (const float*)d_in[5];
    float* out = (float*)d_out;

    cudaFuncSetAttribute(attn_mma_kernel,
                         cudaFuncAttributeMaxDynamicSharedMemorySize, SMEM_BYTES);

    prep_w<<<1024, 256>>>(U_w, F_w);
    prep_x<<<2048, 256>>>(x);

    dim3 grid((Yn + YT - 1) / YT, Bn);   // 140 x 8 = 1120 CTAs, 2/SM
    attn_mma_kernel<<<grid, NT, SMEM_BYTES>>>(f_b, out);

    if (out_size > Bn * Yn)
        bce_kernel<<<1, 1024>>>(out, target, out + Bn * Yn, Bn * Yn);
}

// round 14
// speedup vs baseline: 1.1775x; 1.1775x over previous
#include <cuda_runtime.h>
#include <cuda_fp16.h>
#include <cstdint>

#define Bn 8
#define Ln 2500
#define Dn 512
#define Yn 8921
#define YT 64           // y per CTA
#define LT 128          // l per CTA tile
#define KC 64           // k per chunk (fp16 elems)
#define NCH (Dn / KC)   // 8 chunks
#define NTILES 20       // ceil(2500/128)
#define NT 256
#define ROWB 144                    // smem row stride bytes (128 data + 16 pad)
#define TW (64 * ROWB)              // 9216  (U/F tiles: 64 rows)
#define TX (128 * ROWB)             // 18432 (X tile: 128 rows)
#define OFF_U 0
#define OFF_F TW
#define OFF_X (2 * TW)
#define BUF_BYTES (2 * TW + TX)     // 36864
#define SMEM_BYTES (2 * BUF_BYTES)  // 73728 -> 2 CTAs/SM

// fp16 scratch (device globals; no runtime alloc)
__device__ __half g_u16[(size_t)Yn * Dn];
__device__ __half g_f16[(size_t)Yn * Dn];
__device__ __half g_x16[(size_t)Bn * Ln * Dn];
__device__ float  g_bce_part[264];

// mma.sync m16n8k16 fp16 inputs, fp32 accumulate (plain sm_80+ instruction)
#define MMA(D, A, B0, B1)                                                   \
    asm volatile(                                                           \
        "mma.sync.aligned.m16n8k16.row.col.f32.f16.f16.f32 "                \
        "{%0,%1,%2,%3}, {%4,%5,%6,%7}, {%8,%9}, {%0,%1,%2,%3};"             \
        : "+f"((D)[0]), "+f"((D)[1]), "+f"((D)[2]), "+f"((D)[3])            \
        : "r"((A)[0]), "r"((A)[1]), "r"((A)[2]), "r"((A)[3]),               \
          "r"(B0), "r"(B1))

#define LDSM4(R0, R1, R2, R3, addr)                                         \
    asm volatile(                                                           \
        "ldmatrix.sync.aligned.m8n8.x4.shared.b16 {%0,%1,%2,%3}, [%4];"     \
        : "=r"(R0), "=r"(R1), "=r"(R2), "=r"(R3) : "r"(addr))

static __device__ __forceinline__ void cp16(uint32_t dst, const void* src,
                                            bool v) {
    int sz = v ? 16 : 0;   // sz=0 -> zero-fill 16B, no gmem read
    asm volatile("cp.async.cg.shared.global [%0], [%1], 16, %2;"
                 :: "r"(dst), "l"(src), "r"(sz));
}
template <int N>
static __device__ __forceinline__ void cpwait() {
    asm volatile("cp.async.wait_group %0;" :: "n"(N) : "memory");
}
static __device__ __forceinline__ uint32_t smem_u32(const void* p) {
    uint32_t a;
    asm("{ .reg .u64 t; cvta.to.shared.u64 t, %1; cvt.u32.u64 %0, t; }"
        : "=r"(a) : "l"(p));
    return a;
}

// stage one k-chunk: U,F [64 x 64] + X [128 x 64] fp16 -> padded smem
static __device__ __forceinline__ void stage_chunk(
    uint32_t bufaddr, int tid, int b, int y0, int l0, int k0)
{
    const __half* u = g_u16 + (size_t)y0 * Dn;
    const __half* f = g_f16 + (size_t)y0 * Dn;
    const int limW = Yn - y0;
#pragma unroll
    for (int j = 0; j < 2; j++) {
        int idx = tid + j * NT;              // 0..511 = 64 rows x 8 segs
        int r = idx >> 3, seg = idx & 7;     // seg = 16B (8 fp16)
        uint32_t doff = (uint32_t)(r * ROWB + seg * 16);
        cp16(bufaddr + OFF_U + doff, u + (size_t)r * Dn + k0 + seg * 8, r < limW);
        cp16(bufaddr + OFF_F + doff, f + (size_t)r * Dn + k0 + seg * 8, r < limW);
    }
    const __half* xs = g_x16 + ((size_t)b * Ln + l0) * Dn;
    const int limX = Ln - l0;
#pragma unroll
    for (int j = 0; j < 4; j++) {
        int idx = tid + j * NT;              // 0..1023 = 128 rows x 8 segs
        int r = idx >> 3, seg = idx & 7;
        cp16(bufaddr + OFF_X + (uint32_t)(r * ROWB + seg * 16),
             xs + (size_t)r * Dn + k0 + seg * 8, r < limX);
    }
    asm volatile("cp.async.commit_group;" ::: "memory");
}

__global__ __launch_bounds__(NT, 2)
void attn_mma_kernel(const float* __restrict__ f_b, float* __restrict__ out)
{
    extern __shared__ float smem[];
    const uint32_t sbase = smem_u32(smem);
    const int tid  = threadIdx.x;
    const int lane = tid & 31;
    const int g    = lane >> 2;          // group id 0..7
    const int tg   = lane & 3;           // thread in group 0..3
    const int wid  = tid >> 5;
    const int wy   = wid >> 2;           // warp y index 0..1 (32 y each)
    const int wl   = wid & 3;            // warp l index 0..3 (32 l each)
    const int b    = blockIdx.y;
    const int y0   = blockIdx.x * YT;

    // ldmatrix per-lane address components (bytes)
    const int quad = lane >> 3, r8 = lane & 7;
    const uint32_t laneA = (uint32_t)((r8 + (quad & 1) * 8) * ROWB + (quad >> 1) * 16);
    const uint32_t laneB = (uint32_t)((r8 + (quad >> 1) * 8) * ROWB + (quad & 1) * 16);
    uint32_t aRow[2], bRow[2];
#pragma unroll
    for (int a = 0; a < 2; a++)  aRow[a]  = (uint32_t)((wy * 32 + a * 16) * ROWB) + laneA;
#pragma unroll
    for (int cp = 0; cp < 2; cp++) bRow[cp] = (uint32_t)((wl * 32 + cp * 16) * ROWB) + laneB;

    // running softmax sums for this thread's 4 y rows
    float ss[4] = {0.f, 0.f, 0.f, 0.f};
    float zz[4] = {0.f, 0.f, 0.f, 0.f};

    stage_chunk(sbase, tid, b, y0, 0, 0);   // tile 0, chunk 0 -> buf 0

    for (int t = 0; t < NTILES; t++) {
        const int l0 = t * LT;

        float dS[2][4][4], dT[2][4][4];
#pragma unroll
        for (int a = 0; a < 2; a++)
#pragma unroll
            for (int c = 0; c < 4; c++)
#pragma unroll
                for (int r = 0; r < 4; r++) { dS[a][c][r] = 0.f; dT[a][c][r] = 0.f; }

        for (int ch = 0; ch < NCH; ch++) {
            cpwait<0>();
            __syncthreads();   // all warps done with the other buffer

            const uint32_t bufb = sbase + (ch & 1) * BUF_BYTES;

            // ---- peeled ka=0: start frag loads + mma BEFORE issuing the
            //      next-chunk cp.async burst (stage latency is hidden; its
            //      issue slot position was on the critical path) ----
            uint32_t au0[2][4], af0[2][4], bx0[4][2];
#pragma unroll
            for (int a = 0; a < 2; a++) {
                uint32_t ab = bufb + aRow[a];
                LDSM4(au0[a][0], au0[a][1], au0[a][2], au0[a][3], ab + OFF_U);
                LDSM4(af0[a][0], af0[a][1], af0[a][2], af0[a][3], ab + OFF_F);
            }
#pragma unroll
            for (int cp = 0; cp < 2; cp++) {
                uint32_t bb = bufb + OFF_X + bRow[cp];
                LDSM4(bx0[2*cp][0], bx0[2*cp][1], bx0[2*cp+1][0], bx0[2*cp+1][1], bb);
            }
#pragma unroll
            for (int a = 0; a < 2; a++)
#pragma unroll
                for (int c = 0; c < 4; c++) MMA(dS[a][c], au0[a], bx0[c][0], bx0[c][1]);
#pragma unroll
            for (int a = 0; a < 2; a++)
#pragma unroll
                for (int c = 0; c < 4; c++) MMA(dT[a][c], af0[a], bx0[c][0], bx0[c][1]);

            // now issue the prefetch for the next chunk
            const bool last_all = (t == NTILES - 1) && (ch == NCH - 1);
            if (!last_all) {
                int nl0 = (ch == NCH - 1) ? l0 + LT : l0;
                int nk0 = (ch == NCH - 1) ? 0 : (ch + 1) * KC;
                stage_chunk(sbase + ((ch + 1) & 1) * BUF_BYTES, tid, b, y0, nl0, nk0);
            }

            // remaining k16 steps
#pragma unroll
            for (int ka = 1; ka < 4; ka++) {
                const uint32_t kao = (uint32_t)(ka * 32);
                uint32_t au[2][4], af[2][4];
#pragma unroll
                for (int a = 0; a < 2; a++) {
                    uint32_t ab = bufb + aRow[a] + kao;
                    LDSM4(au[a][0], au[a][1], au[a][2], au[a][3], ab + OFF_U);
                    LDSM4(af[a][0], af[a][1], af[a][2], af[a][3], ab + OFF_F);
                }
                uint32_t bx[4][2];
#pragma unroll
                for (int cp = 0; cp < 2; cp++) {
                    uint32_t bb = bufb + OFF_X + bRow[cp] + kao;
                    LDSM4(bx[2*cp][0], bx[2*cp][1], bx[2*cp+1][0], bx[2*cp+1][1], bb);
                }
#pragma unroll
                for (int a = 0; a < 2; a++)
#pragma unroll
                    for (int c = 0; c < 4; c++) MMA(dS[a][c], au[a], bx[c][0], bx[c][1]);
#pragma unroll
                for (int a = 0; a < 2; a++)
#pragma unroll
                    for (int c = 0; c < 4; c++) MMA(dT[a][c], af[a], bx[c][0], bx[c][1]);
            }
        }

        // epilogue (regs only) — overlaps the in-flight prefetch of next tile
#pragma unroll
        for (int a = 0; a < 2; a++)
#pragma unroll
            for (int c = 0; c < 4; c++)
#pragma unroll
                for (int r2 = 0; r2 < 2; r2++) {
                    int le = l0 + wl * 32 + c * 8 + 2 * tg;
                    float s0 = dS[a][c][r2 * 2],     t0 = dT[a][c][r2 * 2];
                    float s1 = dS[a][c][r2 * 2 + 1], t1 = dT[a][c][r2 * 2 + 1];
                    if (le < Ln)     { float e = __expf(s0); ss[a*2+r2] += e; zz[a*2+r2] += e * t0; }
                    if (le + 1 < Ln) { float e = __expf(s1); ss[a*2+r2] += e; zz[a*2+r2] += e * t1; }
                }
    }

    // reduce across the 4 lanes sharing each y row (tg dimension)
#pragma unroll
    for (int i = 0; i < 4; i++) {
        ss[i] += __shfl_xor_sync(0xffffffffu, ss[i], 1);
        ss[i] += __shfl_xor_sync(0xffffffffu, ss[i], 2);
        zz[i] += __shfl_xor_sync(0xffffffffu, zz[i], 1);
        zz[i] += __shfl_xor_sync(0xffffffffu, zz[i], 2);
    }

    // cross-warp (wl) reduction via smem (all staging finished by now)
    __syncthreads();
    float* sred = smem;          // [4 wl][64]
    float* zred = smem + 256;    // [4 wl][64]
    if (tg == 0) {
#pragma unroll
        for (int i = 0; i < 4; i++) {
            int yl = wy * 32 + (i >> 1) * 16 + (i & 1) * 8 + g;
            sred[wl * 64 + yl] = ss[i];
            zred[wl * 64 + yl] = zz[i];
        }
    }
    __syncthreads();
    if (tid < YT) {
        int yg = y0 + tid;
        if (yg < Yn) {
            float s = sred[tid] + sred[64 + tid] + sred[128 + tid] + sred[192 + tid];
            float z = zred[tid] + zred[64 + tid] + zred[128 + tid] + zred[192 + tid];
            out[(size_t)b * Yn + yg] = z / s + f_b[yg];
        }
    }
}

// ---------------- prepass: fp32 -> fp16 (float4-vectorized) ----------------
__global__ void prep_w(const float* __restrict__ U, const float* __restrict__ F)
{
    const size_t n4 = (size_t)Yn * Dn / 4;
    const float4* U4 = (const float4*)U;
    const float4* F4 = (const float4*)F;
    for (size_t i = (size_t)blockIdx.x * blockDim.x + threadIdx.x; i < n4;
         i += (size_t)gridDim.x * blockDim.x) {
        float4 u = U4[i], f = F4[i];
        __half2* uo = (__half2*)g_u16;
        __half2* fo = (__half2*)g_f16;
        uo[2*i]   = __floats2half2_rn(u.x, u.y);
        uo[2*i+1] = __floats2half2_rn(u.z, u.w);
        fo[2*i]   = __floats2half2_rn(f.x, f.y);
        fo[2*i+1] = __floats2half2_rn(f.z, f.w);
    }
}

__global__ void prep_x(const float* __restrict__ x)
{
    const size_t n4 = (size_t)Bn * Ln * Dn / 4;
    const float4* X4 = (const float4*)x;
    for (size_t i = (size_t)blockIdx.x * blockDim.x + threadIdx.x; i < n4;
         i += (size_t)gridDim.x * blockDim.x) {
        float4 v = X4[i];
        __half2* xo = (__half2*)g_x16;
        xo[2*i]   = __floats2half2_rn(v.x, v.y);
        xo[2*i+1] = __floats2half2_rn(v.z, v.w);
    }
}

// ---------------- BCE loss: 2-stage deterministic ----------------
__global__ void bce_part_kernel(const float* __restrict__ y,
                                const float* __restrict__ t, int n)
{
    __shared__ float red[256];
    float acc = 0.f;
    for (int i = blockIdx.x * 256 + threadIdx.x; i < n; i += gridDim.x * 256) {
        float v  = y[i];
        float tt = t[i];
        acc += fmaxf(v, 0.f) - v * tt + log1pf(__expf(-fabsf(v)));
    }
    red[threadIdx.x] = acc;
    __syncthreads();
    for (int s = 128; s > 0; s >>= 1) {
        if (threadIdx.x < s) red[threadIdx.x] += red[threadIdx.x + s];
        __syncthreads();
    }
    if (threadIdx.x == 0) g_bce_part[blockIdx.x] = red[0];
}

__global__ void bce_final_kernel(float* __restrict__ loss_out, int npart, int n)
{
    __shared__ float red[264];
    red[threadIdx.x] = (threadIdx.x < npart) ? g_bce_part[threadIdx.x] : 0.f;
    __syncthreads();
    if (threadIdx.x == 0) {
        float s = 0.f;
        for (int i = 0; i < npart; i++) s += red[i];   // fixed order
        loss_out[0] = s / (float)n;
    }
}

extern "C" void kernel_launch(void* const* d_in, const int* in_sizes, int n_in,
                              void* d_out, int out_size)
{
    const float* x      = (const float*)d_in[0];
    const float* target = (const float*)d_in[1];
    // d_in[2] = text_inputs (unused)
    const float* U_w    = (const float*)d_in[3];
    const float* F_w    = (const float*)d_in[4];
    const float* f_b    = (const float*)d_in[5];
    float* out = (float*)d_out;

    cudaFuncSetAttribute(attn_mma_kernel,
                         cudaFuncAttributeMaxDynamicSharedMemorySize, SMEM_BYTES);

    prep_w<<<592, 256>>>(U_w, F_w);
    prep_x<<<592, 256>>>(x);

    dim3 grid((Yn + YT - 1) / YT, Bn);   // 140 x 8 = 1120 CTAs, 2/SM
    attn_mma_kernel<<<grid, NT, SMEM_BYTES>>>(f_b, out);

    if (out_size > Bn * Yn) {
        bce_part_kernel<<<264, 256>>>(out, target, Bn * Yn);
        bce_final_kernel<<<1, 264>>>(out + Bn * Yn, 264, Bn * Yn);
    }
}

// round 16
// speedup vs baseline: 1.2798x; 1.0868x over previous
#include <cuda_runtime.h>
#include <cuda_fp16.h>
#include <cstdint>

#define Bn 8
#define Ln 2500
#define Dn 512
#define Yn 8921
#define YT 64           // y per CTA
#define LT 128          // l per CTA tile
#define KC 64           // k per chunk (fp16 elems)
#define NCH (Dn / KC)   // 8 chunks
#define NTILES 20       // ceil(2500/128)
#define NCHUNKS (NTILES * NCH)      // 160
#define NT 256
#define ROWB 144                    // smem row stride bytes (128 data + 16 pad)
#define TW (64 * ROWB)              // 9216  (U/F tiles: 64 rows)
#define TX (128 * ROWB)             // 18432 (X tile: 128 rows)
#define OFF_U 0
#define OFF_F TW
#define OFF_X (2 * TW)
#define BUF_BYTES (2 * TW + TX)     // 36864
#define NBUF 3
#define BAR_OFF (NBUF * BUF_BYTES)          // 110592
#define SMEM_BYTES (BAR_OFF + 64)           // 110656 -> 2 CTAs/SM

// fp16 scratch (device globals; no runtime alloc)
__device__ __half g_u16[(size_t)Yn * Dn];
__device__ __half g_f16[(size_t)Yn * Dn];
__device__ __half g_x16[(size_t)Bn * Ln * Dn];
__device__ float  g_bce_part[264];

// mma.sync m16n8k16 fp16 inputs, fp32 accumulate (plain sm_80+ instruction)
#define MMA(D, A, B0, B1)                                                   \
    asm volatile(                                                           \
        "mma.sync.aligned.m16n8k16.row.col.f32.f16.f16.f32 "                \
        "{%0,%1,%2,%3}, {%4,%5,%6,%7}, {%8,%9}, {%0,%1,%2,%3};"             \
        : "+f"((D)[0]), "+f"((D)[1]), "+f"((D)[2]), "+f"((D)[3])            \
        : "r"((A)[0]), "r"((A)[1]), "r"((A)[2]), "r"((A)[3]),               \
          "r"(B0), "r"(B1))

#define LDSM4(R0, R1, R2, R3, addr)                                         \
    asm volatile(                                                           \
        "ldmatrix.sync.aligned.m8n8.x4.shared.b16 {%0,%1,%2,%3}, [%4];"     \
        : "=r"(R0), "=r"(R1), "=r"(R2), "=r"(R3) : "r"(addr))

static __device__ __forceinline__ void cp16(uint32_t dst, const void* src,
                                            bool v) {
    int sz = v ? 16 : 0;   // sz=0 -> zero-fill 16B, no gmem read
    asm volatile("cp.async.cg.shared.global [%0], [%1], 16, %2;"
                 :: "r"(dst), "l"(src), "r"(sz));
}
static __device__ __forceinline__ uint32_t smem_u32(const void* p) {
    uint32_t a;
    asm("{ .reg .u64 t; cvta.to.shared.u64 t, %1; cvt.u32.u64 %0, t; }"
        : "=r"(a) : "l"(p));
    return a;
}

// ---- mbarrier helpers (sm_80+ PTX; valid at plain compute_103) ----
#define MBINIT(addr, cnt)                                                   \
    asm volatile("mbarrier.init.shared.b64 [%0], %1;"                       \
                 :: "r"(addr), "r"((uint32_t)(cnt)) : "memory")
#define MBARRIVE(addr)                                                      \
    asm volatile("mbarrier.arrive.shared.b64 _, [%0];"                      \
                 :: "r"(addr) : "memory")
// .noinc is LOAD-BEARING: without it the pending count is incremented at
// issue and the async arrive only cancels it (net 0) -> barrier never flips
// (round-15 deadlock). With .noinc, the async completion counts against the
// init() expected count of 256.
#define CPARRIVE(addr)                                                      \
    asm volatile("cp.async.mbarrier.arrive.noinc.shared.b64 [%0];"          \
                 :: "r"(addr) : "memory")
#define MBWAIT(addr, par) do {                                              \
    uint32_t _d = 0;                                                        \
    while (!_d) {                                                           \
        asm volatile(                                                       \
            "{ .reg .pred p; mbarrier.try_wait.parity.shared.b64 p, [%1], %2;" \
            " selp.b32 %0, 1, 0, p; }"                                      \
            : "=r"(_d) : "r"(addr), "r"((uint32_t)(par)) : "memory");       \
    }                                                                       \
} while (0)

// stage one k-chunk: U,F [64 x 64] + X [128 x 64] fp16 -> padded smem
static __device__ __forceinline__ void stage_chunk(
    uint32_t bufaddr, int tid, int b, int y0, int l0, int k0)
{
    const __half* u = g_u16 + (size_t)y0 * Dn;
    const __half* f = g_f16 + (size_t)y0 * Dn;
    const int limW = Yn - y0;
#pragma unroll
    for (int j = 0; j < 2; j++) {
        int idx = tid + j * NT;              // 0..511 = 64 rows x 8 segs
        int r = idx >> 3, seg = idx & 7;     // seg = 16B (8 fp16)
        uint32_t doff = (uint32_t)(r * ROWB + seg * 16);
        cp16(bufaddr + OFF_U + doff, u + (size_t)r * Dn + k0 + seg * 8, r < limW);
        cp16(bufaddr + OFF_F + doff, f + (size_t)r * Dn + k0 + seg * 8, r < limW);
    }
    const __half* xs = g_x16 + ((size_t)b * Ln + l0) * Dn;
    const int limX = Ln - l0;
#pragma unroll
    for (int j = 0; j < 4; j++) {
        int idx = tid + j * NT;              // 0..1023 = 128 rows x 8 segs
        int r = idx >> 3, seg = idx & 7;
        cp16(bufaddr + OFF_X + (uint32_t)(r * ROWB + seg * 16),
             xs + (size_t)r * Dn + k0 + seg * 8, r < limX);
    }
}

__global__ __launch_bounds__(NT, 2)
void attn_mma_kernel(const float* __restrict__ f_b, float* __restrict__ out)
{
    extern __shared__ float smem[];
    const uint32_t sbase = smem_u32(smem);
    const uint32_t barF  = sbase + BAR_OFF;        // full[b]  at +b*8
    const uint32_t barE  = sbase + BAR_OFF + 24;   // empty[b] at +b*8
    const int tid  = threadIdx.x;
    const int lane = tid & 31;
    const int g    = lane >> 2;          // group id 0..7
    const int tg   = lane & 3;           // thread in group 0..3
    const int wid  = tid >> 5;
    const int wy   = wid >> 2;           // warp y index 0..1 (32 y each)
    const int wl   = wid & 3;            // warp l index 0..3 (32 l each)
    const int b    = blockIdx.y;
    const int y0   = blockIdx.x * YT;

    // ldmatrix per-lane address components (bytes)
    const int quad = lane >> 3, r8 = lane & 7;
    const uint32_t laneA = (uint32_t)((r8 + (quad & 1) * 8) * ROWB + (quad >> 1) * 16);
    const uint32_t laneB = (uint32_t)((r8 + (quad >> 1) * 8) * ROWB + (quad & 1) * 16);
    uint32_t aRow[2], bRow[2];
#pragma unroll
    for (int a = 0; a < 2; a++)  aRow[a]  = (uint32_t)((wy * 32 + a * 16) * ROWB) + laneA;
#pragma unroll
    for (int cp = 0; cp < 2; cp++) bRow[cp] = (uint32_t)((wl * 32 + cp * 16) * ROWB) + laneB;

    // running softmax sums for this thread's 4 y rows
    float ss[4] = {0.f, 0.f, 0.f, 0.f};
    float zz[4] = {0.f, 0.f, 0.f, 0.f};

    // init barriers (256 expected arrivals each)
    if (tid == 0) {
#pragma unroll
        for (int q = 0; q < NBUF; q++) {
            MBINIT(barF + q * 8, NT);
            MBINIT(barE + q * 8, NT);
        }
    }
    __syncthreads();

    // prologue: stage chunk 0 (stage-1-ahead pipeline)
    stage_chunk(sbase, tid, b, y0, 0, 0);
    CPARRIVE(barF + 0);

    for (int t = 0; t < NTILES; t++) {
        const int l0 = t * LT;

        float dS[2][4][4], dT[2][4][4];
#pragma unroll
        for (int a = 0; a < 2; a++)
#pragma unroll
            for (int c = 0; c < 4; c++)
#pragma unroll
                for (int r = 0; r < 4; r++) { dS[a][c][r] = 0.f; dT[a][c][r] = 0.f; }

        for (int ch = 0; ch < NCH; ch++) {
            const int ci = t * NCH + ch;

            // ---- stage chunk ci+1 into buf (ci+1)%3 ----
            // That buffer was last read by chunk ci-2, whose readers arrived
            // on empty[] a FULL CHUNK ago -> 1-chunk straggler slack.
            const int ci1 = ci + 1;
            if (ci1 < NCHUNKS) {
                const int b1 = ci1 % 3;
                if (ci1 >= 3)
                    MBWAIT(barE + b1 * 8, ((ci - 2) / 3) & 1);
                int nt2 = ci1 >> 3;          // / NCH
                int nc2 = ci1 & 7;           // % NCH
                stage_chunk(sbase + (uint32_t)b1 * BUF_BYTES, tid, b, y0,
                            nt2 * LT, nc2 * KC);
                CPARRIVE(barF + b1 * 8);
            }

            // ---- wait chunk ci data (arrivals are async cp-completions) ----
            const int bb = ci % 3;
            MBWAIT(barF + bb * 8, (ci / 3) & 1);
            const uint32_t bufb = sbase + (uint32_t)bb * BUF_BYTES;

#pragma unroll
            for (int ka = 0; ka < 4; ka++) {        // four k16 steps
                const uint32_t kao = (uint32_t)(ka * 32);
                uint32_t au[2][4], af[2][4];
#pragma unroll
                for (int a = 0; a < 2; a++) {
                    uint32_t ab = bufb + aRow[a] + kao;
                    LDSM4(au[a][0], au[a][1], au[a][2], au[a][3], ab + OFF_U);
                    LDSM4(af[a][0], af[a][1], af[a][2], af[a][3], ab + OFF_F);
                }
                uint32_t bx[4][2];
#pragma unroll
                for (int cp = 0; cp < 2; cp++) {
                    uint32_t bb2 = bufb + OFF_X + bRow[cp] + kao;
                    LDSM4(bx[2*cp][0], bx[2*cp][1], bx[2*cp+1][0], bx[2*cp+1][1], bb2);
                }
#pragma unroll
                for (int a = 0; a < 2; a++)
#pragma unroll
                    for (int c = 0; c < 4; c++) MMA(dS[a][c], au[a], bx[c][0], bx[c][1]);
#pragma unroll
                for (int a = 0; a < 2; a++)
#pragma unroll
                    for (int c = 0; c < 4; c++) MMA(dT[a][c], af[a], bx[c][0], bx[c][1]);
            }

            // readers of buf bb done -> release for restaging (chunk ci+3)
            MBARRIVE(barE + bb * 8);
        }

        // epilogue (regs only) — fully overlapped, no pipeline stall
#pragma unroll
        for (int a = 0; a < 2; a++)
#pragma unroll
            for (int c = 0; c < 4; c++)
#pragma unroll
                for (int r2 = 0; r2 < 2; r2++) {
                    int le = l0 + wl * 32 + c * 8 + 2 * tg;
                    float s0 = dS[a][c][r2 * 2],     t0 = dT[a][c][r2 * 2];
                    float s1 = dS[a][c][r2 * 2 + 1], t1 = dT[a][c][r2 * 2 + 1];
                    if (le < Ln)     { float e = __expf(s0); ss[a*2+r2] += e; zz[a*2+r2] += e * t0; }
                    if (le + 1 < Ln) { float e = __expf(s1); ss[a*2+r2] += e; zz[a*2+r2] += e * t1; }
                }
    }

    // reduce across the 4 lanes sharing each y row (tg dimension)
#pragma unroll
    for (int i = 0; i < 4; i++) {
        ss[i] += __shfl_xor_sync(0xffffffffu, ss[i], 1);
        ss[i] += __shfl_xor_sync(0xffffffffu, ss[i], 2);
        zz[i] += __shfl_xor_sync(0xffffffffu, zz[i], 1);
        zz[i] += __shfl_xor_sync(0xffffffffu, zz[i], 2);
    }

    // cross-warp (wl) reduction via smem (all chunks consumed by now)
    __syncthreads();
    float* sred = smem;          // [4 wl][64]
    float* zred = smem + 256;    // [4 wl][64]
    if (tg == 0) {
#pragma unroll
        for (int i = 0; i < 4; i++) {
            int yl = wy * 32 + (i >> 1) * 16 + (i & 1) * 8 + g;
            sred[wl * 64 + yl] = ss[i];
            zred[wl * 64 + yl] = zz[i];
        }
    }
    __syncthreads();
    if (tid < YT) {
        int yg = y0 + tid;
        if (yg < Yn) {
            float s = sred[tid] + sred[64 + tid] + sred[128 + tid] + sred[192 + tid];
            float z = zred[tid] + zred[64 + tid] + zred[128 + tid] + zred[192 + tid];
            out[(size_t)b * Yn + yg] = z / s + f_b[yg];
        }
    }
}

// ---------------- prepass: fp32 -> fp16 (float4-vectorized) ----------------
__global__ void prep_w(const float* __restrict__ U, const float* __restrict__ F)
{
    const size_t n4 = (size_t)Yn * Dn / 4;
    const float4* U4 = (const float4*)U;
    const float4* F4 = (const float4*)F;
    for (size_t i = (size_t)blockIdx.x * blockDim.x + threadIdx.x; i < n4;
         i += (size_t)gridDim.x * blockDim.x) {
        float4 u = U4[i], f = F4[i];
        __half2* uo = (__half2*)g_u16;
        __half2* fo = (__half2*)g_f16;
        uo[2*i]   = __floats2half2_rn(u.x, u.y);
        uo[2*i+1] = __floats2half2_rn(u.z, u.w);
        fo[2*i]   = __floats2half2_rn(f.x, f.y);
        fo[2*i+1] = __floats2half2_rn(f.z, f.w);
    }
}

__global__ void prep_x(const float* __restrict__ x)
{
    const size_t n4 = (size_t)Bn * Ln * Dn / 4;
    const float4* X4 = (const float4*)x;
    for (size_t i = (size_t)blockIdx.x * blockDim.x + threadIdx.x; i < n4;
         i += (size_t)gridDim.x * blockDim.x) {
        float4 v = X4[i];
        __half2* xo = (__half2*)g_x16;
        xo[2*i]   = __floats2half2_rn(v.x, v.y);
        xo[2*i+1] = __floats2half2_rn(v.z, v.w);
    }
}

// ---------------- BCE loss: 2-stage deterministic ----------------
__global__ void bce_part_kernel(const float* __restrict__ y,
                                const float* __restrict__ t, int n)
{
    __shared__ float red[256];
    float acc = 0.f;
    for (int i = blockIdx.x * 256 + threadIdx.x; i < n; i += gridDim.x * 256) {
        float v  = y[i];
        float tt = t[i];
        acc += fmaxf(v, 0.f) - v * tt + log1pf(__expf(-fabsf(v)));
    }
    red[threadIdx.x] = acc;
    __syncthreads();
    for (int s = 128; s > 0; s >>= 1) {
        if (threadIdx.x < s) red[threadIdx.x] += red[threadIdx.x + s];
        __syncthreads();
    }
    if (threadIdx.x == 0) g_bce_part[blockIdx.x] = red[0];
}

__global__ void bce_final_kernel(float* __restrict__ loss_out, int npart, int n)
{
    __shared__ float red[264];
    red[threadIdx.x] = (threadIdx.x < npart) ? g_bce_part[threadIdx.x] : 0.f;
    __syncthreads();
    if (threadIdx.x == 0) {
        float s = 0.f;
        for (int i = 0; i < npart; i++) s += red[i];   // fixed order
        loss_out[0] = s / (float)n;
    }
}

extern "C" void kernel_launch(void* const* d_in, const int* in_sizes, int n_in,
                              void* d_out, int out_size)
{
    const float* x      = (const float*)d_in[0];
    const float* target = (const float*)d_in[1];
    // d_in[2] = text_inputs (unused)
    const float* U_w    = (const float*)d_in[3];
    const float* F_w    = (const float*)d_in[4];
    const float* f_b    = (const float*)d_in[5];
    float* out = (float*)d_out;

    cudaFuncSetAttribute(attn_mma_kernel,
                         cudaFuncAttributeMaxDynamicSharedMemorySize, SMEM_BYTES);

    prep_w<<<592, 256>>>(U_w, F_w);
    prep_x<<<592, 256>>>(x);

    dim3 grid((Yn + YT - 1) / YT, Bn);   // 140 x 8 = 1120 CTAs, 2/SM
    attn_mma_kernel<<<grid, NT, SMEM_BYTES>>>(f_b, out);

    if (out_size > Bn * Yn) {
        bce_part_kernel<<<264, 256>>>(out, target, Bn * Yn);
        bce_final_kernel<<<1, 264>>>(out + Bn * Yn, 264, Bn * Yn);
    }
}

// round 17
// speedup vs baseline: 1.2809x; 1.0009x over previous
#include <cuda_runtime.h>
#include <cuda_fp16.h>
#include <cstdint>

#define Bn 8
#define Ln 2500
#define Dn 512
#define Yn 8921
#define YT 64           // y per CTA
#define LT 128          // l per CTA tile
#define KC 64           // k per chunk (fp16 elems)
#define NCH (Dn / KC)   // 8 chunks
#define NTILES 20       // ceil(2500/128)
#define NCHUNKS (NTILES * NCH)      // 160
#define NT 256
#define ROWB 144                    // smem row stride bytes (128 data + 16 pad)
#define TW (64 * ROWB)              // 9216  (U/F tiles: 64 rows)
#define TX (128 * ROWB)             // 18432 (X tile: 128 rows)
#define OFF_U 0
#define OFF_F TW
#define OFF_X (2 * TW)
#define BUF_BYTES (2 * TW + TX)     // 36864
#define NBUF 3
#define BAR_OFF (NBUF * BUF_BYTES)          // 110592
#define SMEM_BYTES (BAR_OFF + 64)           // 110656 -> 2 CTAs/SM

// fp16 scratch (device globals; no runtime alloc)
__device__ __half g_u16[(size_t)Yn * Dn];
__device__ __half g_f16[(size_t)Yn * Dn];
__device__ __half g_x16[(size_t)Bn * Ln * Dn];
__device__ float  g_bce_part[264];

// mma.sync m16n8k16 fp16 inputs, fp32 accumulate (plain sm_80+ instruction)
#define MMA(D, A, B0, B1)                                                   \
    asm volatile(                                                           \
        "mma.sync.aligned.m16n8k16.row.col.f32.f16.f16.f32 "                \
        "{%0,%1,%2,%3}, {%4,%5,%6,%7}, {%8,%9}, {%0,%1,%2,%3};"             \
        : "+f"((D)[0]), "+f"((D)[1]), "+f"((D)[2]), "+f"((D)[3])            \
        : "r"((A)[0]), "r"((A)[1]), "r"((A)[2]), "r"((A)[3]),               \
          "r"(B0), "r"(B1))

#define LDSM4(R0, R1, R2, R3, addr)                                         \
    asm volatile(                                                           \
        "ldmatrix.sync.aligned.m8n8.x4.shared.b16 {%0,%1,%2,%3}, [%4];"     \
        : "=r"(R0), "=r"(R1), "=r"(R2), "=r"(R3) : "r"(addr))

static __device__ __forceinline__ void cp16(uint32_t dst, const void* src,
                                            bool v) {
    int sz = v ? 16 : 0;   // sz=0 -> zero-fill 16B, no gmem read
    asm volatile("cp.async.cg.shared.global [%0], [%1], 16, %2;"
                 :: "r"(dst), "l"(src), "r"(sz));
}
static __device__ __forceinline__ uint32_t smem_u32(const void* p) {
    uint32_t a;
    asm("{ .reg .u64 t; cvta.to.shared.u64 t, %1; cvt.u32.u64 %0, t; }"
        : "=r"(a) : "l"(p));
    return a;
}

// ---- mbarrier helpers (sm_80+ PTX; valid at plain compute_103) ----
#define MBINIT(addr, cnt)                                                   \
    asm volatile("mbarrier.init.shared.b64 [%0], %1;"                       \
                 :: "r"(addr), "r"((uint32_t)(cnt)) : "memory")
#define MBARRIVE(addr)                                                      \
    asm volatile("mbarrier.arrive.shared.b64 _, [%0];"                      \
                 :: "r"(addr) : "memory")
// .noinc is LOAD-BEARING: async completion counts against init() expected
// count (round-15 deadlock without it).
#define CPARRIVE(addr)                                                      \
    asm volatile("cp.async.mbarrier.arrive.noinc.shared.b64 [%0];"          \
                 :: "r"(addr) : "memory")
#define MBWAIT(addr, par) do {                                              \
    uint32_t _d = 0;                                                        \
    while (!_d) {                                                           \
        asm volatile(                                                       \
            "{ .reg .pred p; mbarrier.try_wait.parity.shared.b64 p, [%1], %2;" \
            " selp.b32 %0, 1, 0, p; }"                                      \
            : "=r"(_d) : "r"(addr), "r"((uint32_t)(par)) : "memory");       \
    }                                                                       \
} while (0)

// stage one k-chunk: U,F [64 x 64] + X [128 x 64] fp16 -> padded smem
static __device__ __forceinline__ void stage_chunk(
    uint32_t bufaddr, int tid, int b, int y0, int l0, int k0)
{
    const __half* u = g_u16 + (size_t)y0 * Dn;
    const __half* f = g_f16 + (size_t)y0 * Dn;
    const int limW = Yn - y0;
#pragma unroll
    for (int j = 0; j < 2; j++) {
        int idx = tid + j * NT;              // 0..511 = 64 rows x 8 segs
        int r = idx >> 3, seg = idx & 7;     // seg = 16B (8 fp16)
        uint32_t doff = (uint32_t)(r * ROWB + seg * 16);
        cp16(bufaddr + OFF_U + doff, u + (size_t)r * Dn + k0 + seg * 8, r < limW);
        cp16(bufaddr + OFF_F + doff, f + (size_t)r * Dn + k0 + seg * 8, r < limW);
    }
    const __half* xs = g_x16 + ((size_t)b * Ln + l0) * Dn;
    const int limX = Ln - l0;
#pragma unroll
    for (int j = 0; j < 4; j++) {
        int idx = tid + j * NT;              // 0..1023 = 128 rows x 8 segs
        int r = idx >> 3, seg = idx & 7;
        cp16(bufaddr + OFF_X + (uint32_t)(r * ROWB + seg * 16),
             xs + (size_t)r * Dn + k0 + seg * 8, r < limX);
    }
}

__global__ __launch_bounds__(NT, 2)
void attn_mma_kernel(const float* __restrict__ f_b, float* __restrict__ out)
{
    extern __shared__ float smem[];
    const uint32_t sbase = smem_u32(smem);
    const uint32_t barF  = sbase + BAR_OFF;        // full[b]  at +b*8
    const uint32_t barE  = sbase + BAR_OFF + 24;   // empty[b] at +b*8
    const int tid  = threadIdx.x;
    const int lane = tid & 31;
    const int g    = lane >> 2;          // group id 0..7
    const int tg   = lane & 3;           // thread in group 0..3
    const int wid  = tid >> 5;
    const int wy   = wid >> 2;           // warp y index 0..1 (32 y each)
    const int wl   = wid & 3;            // warp l index 0..3 (32 l each)
    const int b    = blockIdx.y;
    const int y0   = blockIdx.x * YT;

    // ldmatrix per-lane address components (bytes)
    const int quad = lane >> 3, r8 = lane & 7;
    const uint32_t laneA = (uint32_t)((r8 + (quad & 1) * 8) * ROWB + (quad >> 1) * 16);
    const uint32_t laneB = (uint32_t)((r8 + (quad >> 1) * 8) * ROWB + (quad & 1) * 16);
    uint32_t aRow[2], bRow[2];
#pragma unroll
    for (int a = 0; a < 2; a++)  aRow[a]  = (uint32_t)((wy * 32 + a * 16) * ROWB) + laneA;
#pragma unroll
    for (int cp = 0; cp < 2; cp++) bRow[cp] = (uint32_t)((wl * 32 + cp * 16) * ROWB) + laneB;

    // running softmax sums for this thread's 4 y rows
    float ss[4] = {0.f, 0.f, 0.f, 0.f};
    float zz[4] = {0.f, 0.f, 0.f, 0.f};

    // init barriers: full = 256 async arrivals; empty = 8 (one per warp)
    if (tid == 0) {
#pragma unroll
        for (int q = 0; q < NBUF; q++) {
            MBINIT(barF + q * 8, NT);
            MBINIT(barE + q * 8, 8);
        }
    }
    __syncthreads();

    // prologue: stage chunk 0 (stage-1-ahead pipeline)
    stage_chunk(sbase, tid, b, y0, 0, 0);
    CPARRIVE(barF + 0);

    for (int t = 0; t < NTILES; t++) {
        const int l0 = t * LT;

        float dS[2][4][4], dT[2][4][4];
#pragma unroll
        for (int a = 0; a < 2; a++)
#pragma unroll
            for (int c = 0; c < 4; c++)
#pragma unroll
                for (int r = 0; r < 4; r++) { dS[a][c][r] = 0.f; dT[a][c][r] = 0.f; }

        for (int ch = 0; ch < NCH; ch++) {
            const int ci = t * NCH + ch;

            // ---- stage chunk ci+1 into buf (ci+1)%3 ----
            // (buffer last read by chunk ci-2; its empty fired a chunk ago)
            const int ci1 = ci + 1;
            if (ci1 < NCHUNKS) {
                const int b1 = ci1 % 3;
                if (ci1 >= 3)
                    MBWAIT(barE + b1 * 8, ((ci - 2) / 3) & 1);
                int nt2 = ci1 >> 3;          // / NCH
                int nc2 = ci1 & 7;           // % NCH
                stage_chunk(sbase + (uint32_t)b1 * BUF_BYTES, tid, b, y0,
                            nt2 * LT, nc2 * KC);
                CPARRIVE(barF + b1 * 8);
            }

            // ---- wait chunk ci data (arrivals are async cp-completions) ----
            const int bb = ci % 3;
            MBWAIT(barF + bb * 8, (ci / 3) & 1);
            const uint32_t bufb = sbase + (uint32_t)bb * BUF_BYTES;

            // ka = 0..2: load frags + mma
#pragma unroll
            for (int ka = 0; ka < 3; ka++) {
                const uint32_t kao = (uint32_t)(ka * 32);
                uint32_t au[2][4], af[2][4];
#pragma unroll
                for (int a = 0; a < 2; a++) {
                    uint32_t ab = bufb + aRow[a] + kao;
                    LDSM4(au[a][0], au[a][1], au[a][2], au[a][3], ab + OFF_U);
                    LDSM4(af[a][0], af[a][1], af[a][2], af[a][3], ab + OFF_F);
                }
                uint32_t bx[4][2];
#pragma unroll
                for (int cp = 0; cp < 2; cp++) {
                    uint32_t bb2 = bufb + OFF_X + bRow[cp] + kao;
                    LDSM4(bx[2*cp][0], bx[2*cp][1], bx[2*cp+1][0], bx[2*cp+1][1], bb2);
                }
#pragma unroll
                for (int a = 0; a < 2; a++)
#pragma unroll
                    for (int c = 0; c < 4; c++) MMA(dS[a][c], au[a], bx[c][0], bx[c][1]);
#pragma unroll
                for (int a = 0; a < 2; a++)
#pragma unroll
                    for (int c = 0; c < 4; c++) MMA(dT[a][c], af[a], bx[c][0], bx[c][1]);
            }

            // ka = 3: load frags, EARLY empty-release, then mma.
            // The warp's smem reads for this buffer end at its last LDSM;
            // releasing before the mma block gives the stager a ~25%-chunk
            // head start. Per-warp (lane 0) arrive: 8 ops, not 256.
            {
                const uint32_t kao = 96;
                uint32_t au[2][4], af[2][4];
#pragma unroll
                for (int a = 0; a < 2; a++) {
                    uint32_t ab = bufb + aRow[a] + kao;
                    LDSM4(au[a][0], au[a][1], au[a][2], au[a][3], ab + OFF_U);
                    LDSM4(af[a][0], af[a][1], af[a][2], af[a][3], ab + OFF_F);
                }
                uint32_t bx[4][2];
#pragma unroll
                for (int cp = 0; cp < 2; cp++) {
                    uint32_t bb2 = bufb + OFF_X + bRow[cp] + kao;
                    LDSM4(bx[2*cp][0], bx[2*cp][1], bx[2*cp+1][0], bx[2*cp+1][1], bb2);
                }
                if (lane == 0) MBARRIVE(barE + bb * 8);
#pragma unroll
                for (int a = 0; a < 2; a++)
#pragma unroll
                    for (int c = 0; c < 4; c++) MMA(dS[a][c], au[a], bx[c][0], bx[c][1]);
#pragma unroll
                for (int a = 0; a < 2; a++)
#pragma unroll
                    for (int c = 0; c < 4; c++) MMA(dT[a][c], af[a], bx[c][0], bx[c][1]);
            }
        }

        // epilogue (regs only) — fully overlapped, no pipeline stall
#pragma unroll
        for (int a = 0; a < 2; a++)
#pragma unroll
            for (int c = 0; c < 4; c++)
#pragma unroll
                for (int r2 = 0; r2 < 2; r2++) {
                    int le = l0 + wl * 32 + c * 8 + 2 * tg;
                    float s0 = dS[a][c][r2 * 2],     t0 = dT[a][c][r2 * 2];
                    float s1 = dS[a][c][r2 * 2 + 1], t1 = dT[a][c][r2 * 2 + 1];
                    if (le < Ln)     { float e = __expf(s0); ss[a*2+r2] += e; zz[a*2+r2] += e * t0; }
                    if (le + 1 < Ln) { float e = __expf(s1); ss[a*2+r2] += e; zz[a*2+r2] += e * t1; }
                }
    }

    // reduce across the 4 lanes sharing each y row (tg dimension)
#pragma unroll
    for (int i = 0; i < 4; i++) {
        ss[i] += __shfl_xor_sync(0xffffffffu, ss[i], 1);
        ss[i] += __shfl_xor_sync(0xffffffffu, ss[i], 2);
        zz[i] += __shfl_xor_sync(0xffffffffu, zz[i], 1);
        zz[i] += __shfl_xor_sync(0xffffffffu, zz[i], 2);
    }

    // cross-warp (wl) reduction via smem (all chunks consumed by now)
    __syncthreads();
    float* sred = smem;          // [4 wl][64]
    float* zred = smem + 256;    // [4 wl][64]
    if (tg == 0) {
#pragma unroll
        for (int i = 0; i < 4; i++) {
            int yl = wy * 32 + (i >> 1) * 16 + (i & 1) * 8 + g;
            sred[wl * 64 + yl] = ss[i];
            zred[wl * 64 + yl] = zz[i];
        }
    }
    __syncthreads();
    if (tid < YT) {
        int yg = y0 + tid;
        if (yg < Yn) {
            float s = sred[tid] + sred[64 + tid] + sred[128 + tid] + sred[192 + tid];
            float z = zred[tid] + zred[64 + tid] + zred[128 + tid] + zred[192 + tid];
            out[(size_t)b * Yn + yg] = z / s + f_b[yg];
        }
    }
}

// ---------------- prepass: fp32 -> fp16 (float4-vectorized) ----------------
__global__ void prep_w(const float* __restrict__ U, const float* __restrict__ F)
{
    const size_t n4 = (size_t)Yn * Dn / 4;
    const float4* U4 = (const float4*)U;
    const float4* F4 = (const float4*)F;
    for (size_t i = (size_t)blockIdx.x * blockDim.x + threadIdx.x; i < n4;
         i += (size_t)gridDim.x * blockDim.x) {
        float4 u = U4[i], f = F4[i];
        __half2* uo = (__half2*)g_u16;
        __half2* fo = (__half2*)g_f16;
        uo[2*i]   = __floats2half2_rn(u.x, u.y);
        uo[2*i+1] = __floats2half2_rn(u.z, u.w);
        fo[2*i]   = __floats2half2_rn(f.x, f.y);
        fo[2*i+1] = __floats2half2_rn(f.z, f.w);
    }
}

__global__ void prep_x(const float* __restrict__ x)
{
    const size_t n4 = (size_t)Bn * Ln * Dn / 4;
    const float4* X4 = (const float4*)x;
    for (size_t i = (size_t)blockIdx.x * blockDim.x + threadIdx.x; i < n4;
         i += (size_t)gridDim.x * blockDim.x) {
        float4 v = X4[i];
        __half2* xo = (__half2*)g_x16;
        xo[2*i]   = __floats2half2_rn(v.x, v.y);
        xo[2*i+1] = __floats2half2_rn(v.z, v.w);
    }
}

// ---------------- BCE loss: 2-stage deterministic ----------------
__global__ void bce_part_kernel(const float* __restrict__ y,
                                const float* __restrict__ t, int n)
{
    __shared__ float red[256];
    float acc = 0.f;
    for (int i = blockIdx.x * 256 + threadIdx.x; i < n; i += gridDim.x * 256) {
        float v  = y[i];
        float tt = t[i];
        acc += fmaxf(v, 0.f) - v * tt + log1pf(__expf(-fabsf(v)));
    }
    red[threadIdx.x] = acc;
    __syncthreads();
    for (int s = 128; s > 0; s >>= 1) {
        if (threadIdx.x < s) red[threadIdx.x] += red[threadIdx.x + s];
        __syncthreads();
    }
    if (threadIdx.x == 0) g_bce_part[blockIdx.x] = red[0];
}

__global__ void bce_final_kernel(float* __restrict__ loss_out, int npart, int n)
{
    __shared__ float red[264];
    red[threadIdx.x] = (threadIdx.x < npart) ? g_bce_part[threadIdx.x] : 0.f;
    __syncthreads();
    if (threadIdx.x == 0) {
        float s = 0.f;
        for (int i = 0; i < npart; i++) s += red[i];   // fixed order
        loss_out[0] = s / (float)n;
    }
}

extern "C" void kernel_launch(void* const* d_in, const int* in_sizes, int n_in,
                              void* d_out, int out_size)
{
    const float* x      = (const float*)d_in[0];
    const float* target = (const float*)d_in[1];
    // d_in[2] = text_inputs (unused)
    const float* U_w    = (const float*)d_in[3];
    const float* F_w    = (const float*)d_in[4];
    const float* f_b    = (const float*)d_in[5];
    float* out = (float*)d_out;

    cudaFuncSetAttribute(attn_mma_kernel,
                         cudaFuncAttributeMaxDynamicSharedMemorySize, SMEM_BYTES);

    prep_w<<<592, 256>>>(U_w, F_w);
    prep_x<<<592, 256>>>(x);

    dim3 grid((Yn + YT - 1) / YT, Bn);   // 140 x 8 = 1120 CTAs, 2/SM
    attn_mma_kernel<<<grid, NT, SMEM_BYTES>>>(f_b, out);

    if (out_size > Bn * Yn) {
        bce_part_kernel<<<264, 256>>>(out, target, Bn * Yn);
        bce_final_kernel<<<1, 264>>>(out + Bn * Yn, 264, Bn * Yn);
    }
}